// round 17
// baseline (speedup 1.0000x reference)
#include <cuda_runtime.h>
#include <cuda_fp16.h>
#include <math.h>
#include <stdint.h>

// ---------------------------------------------------------------------------
// Problem dims (fixed)
// ---------------------------------------------------------------------------
#define BATCH 8
#define CH    512
#define HI    32
#define WI    32
#define HO    64
#define WO    64
#define HP    66
#define WP    66
#define PLANE_O (HO*WO)          // 4096
#define CPX   512                // fp16 channels per pixel

// ---------------------------------------------------------------------------
// Static device scratch (no allocations allowed)
// ---------------------------------------------------------------------------
__device__ __half g_a1[(size_t)BATCH*HP*WP*CPX];
__device__ __half g_a2[(size_t)BATCH*HP*WP*CPX];
__device__ __half g_w1p[9LL*CH*CH];
__device__ __half g_w2p[9LL*CH*CH];
__device__ float g_wsq[2][CH*CH];
__device__ float g_s1[BATCH*CH];
__device__ float g_s2[BATCH*CH];
__device__ float g_sr[BATCH*CH];
__device__ float g_d1[BATCH*CH];
__device__ float g_d2[BATCH*CH];

// ---------------------------------------------------------------------------
// PTX helpers
// ---------------------------------------------------------------------------
__device__ __forceinline__ uint32_t smem_u32(const void* p) {
    uint32_t a;
    asm("{ .reg .u64 t; cvta.to.shared.u64 t, %1; cvt.u32.u64 %0, t; }"
        : "=r"(a) : "l"(p));
    return a;
}

__device__ __forceinline__ uint32_t pack_f16x2(__half lo, __half hi) {
    return (uint32_t)__half_as_ushort(lo) | ((uint32_t)__half_as_ushort(hi) << 16);
}

#define CP_ASYNC16(dst, src) \
    asm volatile("cp.async.cg.shared.global [%0], [%1], 16;" \
        :: "r"(dst), "l"(src) : "memory")
#define CP_COMMIT() asm volatile("cp.async.commit_group;" ::: "memory")
#define CP_WAIT(N)  asm volatile("cp.async.wait_group %0;" :: "n"(N) : "memory")

__device__ __forceinline__ void ldsm_x4(uint32_t r[4], uint32_t addr) {
    asm volatile("ldmatrix.sync.aligned.m8n8.x4.shared.b16 {%0,%1,%2,%3}, [%4];"
        : "=r"(r[0]), "=r"(r[1]), "=r"(r[2]), "=r"(r[3]) : "r"(addr));
}

__device__ __forceinline__ void mma_f16(float d[4], const uint32_t a[4],
                                        uint32_t b0, uint32_t b1) {
    asm volatile(
        "mma.sync.aligned.m16n8k16.row.col.f32.f16.f16.f32 "
        "{%0,%1,%2,%3}, {%4,%5,%6,%7}, {%8,%9}, {%0,%1,%2,%3};"
        : "+f"(d[0]), "+f"(d[1]), "+f"(d[2]), "+f"(d[3])
        : "r"(a[0]), "r"(a[1]), "r"(a[2]), "r"(a[3]), "r"(b0), "r"(b1));
}

// ---------------------------------------------------------------------------
// K0: styles (0..47) | wpack+wsq via smem staging (48..2095)
//     | activation border-zero (2096..3135) | rgb-zero (3136..3231)
// ---------------------------------------------------------------------------
#define K0_STYLE  48
#define K0_WPACK  2048
#define K0_BORDER 1040       // 2*8*260*64 uint4 / 256
#define K0_RGBZ   96
#define K0_BLOCKS (K0_STYLE + K0_WPACK + K0_BORDER + K0_RGBZ)

__global__ void prep1_kernel(const float* __restrict__ w,
                             const float* __restrict__ m1w, const float* __restrict__ m1b,
                             const float* __restrict__ m2w, const float* __restrict__ m2b,
                             const float* __restrict__ mrw, const float* __restrict__ mrb,
                             const float* __restrict__ w1, const float* __restrict__ w2,
                             float* __restrict__ rgb_out)
{
    if (blockIdx.x < K0_STYLE) {
        int idx = blockIdx.x * 256 + threadIdx.x;
        int sel = idx >> 12;
        int r = idx & 4095;
        const float* mw = (sel == 0) ? m1w : (sel == 1) ? m2w : mrw;
        const float* mb = (sel == 0) ? m1b : (sel == 1) ? m2b : mrb;
        float* outp = (sel == 0) ? g_s1 : (sel == 1) ? g_s2 : g_sr;
        int b = r >> 9, c = r & 511;
        const float* wb = w + (size_t)b * CH;
        const float* mwc = mw + (size_t)c * CH;
        float acc = mb[c];
        #pragma unroll 8
        for (int t = 0; t < CH; t++) acc += wb[t] * mwc[t];
        outp[r] = acc;
        return;
    }
    if (blockIdx.x < K0_STYLE + K0_WPACK) {
        // wpack + wsq, smem-staged for coalescing: block handles 256
        // consecutive (co,ci) pairs = 2304 contiguous floats.
        __shared__ float slab[2304];
        int bidx = blockIdx.x - K0_STYLE;            // 0..2047
        int which = bidx >> 10;                      // 0..1
        int e0 = (bidx & 1023) * 256;                // first pair index
        const float* wgt = (which ? w2 : w1) + (size_t)e0 * 9;
        __half* out = which ? g_w2p : g_w1p;
        #pragma unroll
        for (int i = threadIdx.x; i < 2304; i += 256)
            slab[i] = wgt[i];
        __syncthreads();
        int e = e0 + threadIdx.x;
        const float* p = slab + threadIdx.x * 9;
        float q = 0.f;
        #pragma unroll
        for (int tap = 0; tap < 9; tap++) {
            float v = p[tap];
            q += v * v;
            out[(size_t)tap * (CH * CH) + e] = __float2half(v);
        }
        g_wsq[which][e] = q;
        return;
    }
    if (blockIdx.x < K0_STYLE + K0_WPACK + K0_BORDER) {
        // activation border-zero: 2 buffers x 8 b x 260 px x 64 uint4
        int i = (blockIdx.x - (K0_STYLE + K0_WPACK)) * 256 + threadIdx.x;
        int buf = (i >= 133120);
        int j = i - buf * 133120;
        int b  = j / 16640;
        int k  = j - b * 16640;
        int bp = k >> 6;
        int u  = k & 63;
        int row, colp;
        if (bp < 66)       { row = 0;  colp = bp; }
        else if (bp < 132) { row = 65; colp = bp - 66; }
        else { int jj = bp - 132; row = 1 + (jj >> 1); colp = (jj & 1) ? 65 : 0; }
        size_t off = (((size_t)(b * HP + row)) * WP + colp) * CPX;
        ((uint4*)((buf ? g_a2 : g_a1) + off))[u] = make_uint4(0, 0, 0, 0);
        return;
    }
    // rgb-zero
    int u = (blockIdx.x - (K0_STYLE + K0_WPACK + K0_BORDER)) * 256 + threadIdx.x;
    ((uint4*)rgb_out)[u] = make_uint4(0, 0, 0, 0);
}

// ---------------------------------------------------------------------------
// K1: demod (0..8191) + upsample (8192..12287)
// ---------------------------------------------------------------------------
#define K1_BLOCKS (8192 + 4096)
__global__ void prep2_kernel(const float* __restrict__ x)
{
    if (blockIdx.x < 8192) {
        __shared__ float red[256];
        const int which = blockIdx.x >> 12;
        const int bc = blockIdx.x & 4095;
        const int b  = bc >> 9;
        const int co = bc & 511;
        const int t  = threadIdx.x;
        const float* qrow = g_wsq[which] + (size_t)co * CH;
        const float* s = which ? g_s2 : g_s1;
        float* d       = which ? g_d2 : g_d1;
        float partial = 0.f;
        #pragma unroll
        for (int h = 0; h < 2; h++) {
            int ci = t + h * 256;
            float sv = s[b * CH + ci];
            partial += qrow[ci] * sv * sv;
        }
        red[t] = partial;
        __syncthreads();
        for (int off = 128; off >= 32; off >>= 1) {
            if (t < off) red[t] += red[t + off];
            __syncthreads();
        }
        if (t < 32) {
            float v = red[t];
            #pragma unroll
            for (int off = 16; off > 0; off >>= 1)
                v += __shfl_down_sync(0xffffffffu, v, off);
            if (t == 0) d[b * CH + co] = rsqrtf(v + 1e-8f);
        }
        return;
    }

    __shared__ float rows[64][2][33];
    int u = blockIdx.x - 8192;            // 0..4095
    int b  = u >> 9;                      // 8
    int r  = u & 511;
    int y  = r >> 3;                      // 0..63
    int c0 = (r & 7) * 64;

    float syf = y * 0.5f - 0.25f;
    int y0i = (int)floorf(syf);
    float fy = syf - (float)y0i;
    int ya = max(y0i, 0), yb = min(y0i + 1, HI - 1);
    for (int i = threadIdx.x; i < 64 * 2 * 32; i += 256) {
        int ci = i >> 6, rr = (i >> 5) & 1, xx = i & 31;
        rows[ci][rr][xx] = x[(((size_t)(b * CH + c0 + ci)) * HI + (rr ? yb : ya)) * WI + xx];
    }
    __syncthreads();
    int px = threadIdx.x >> 2;
    int g  = (threadIdx.x & 3) * 16;
    float sxf = px * 0.5f - 0.25f;
    int x0i = (int)floorf(sxf);
    float fx = sxf - (float)x0i;
    int xa = max(x0i, 0), xb = min(x0i + 1, WI - 1);
    size_t obase = (((size_t)(b * HP + y + 1)) * WP + (px + 1)) * CPX + c0 + g;

    uint32_t hbuf[8];
    #pragma unroll
    for (int j2 = 0; j2 < 8; j2++) {
        float vv[2];
        #pragma unroll
        for (int e = 0; e < 2; e++) {
            int ci = g + j2 * 2 + e;
            float v0 = rows[ci][0][xa] * (1.f - fx) + rows[ci][0][xb] * fx;
            float v1 = rows[ci][1][xa] * (1.f - fx) + rows[ci][1][xb] * fx;
            vv[e] = (v0 * (1.f - fy) + v1 * fy) * g_s1[b * CH + c0 + ci];
        }
        hbuf[j2] = pack_f16x2(__float2half(vv[0]), __float2half(vv[1]));
    }
    uint4* oh = (uint4*)(g_a1 + obase);
    oh[0] = make_uint4(hbuf[0], hbuf[1], hbuf[2], hbuf[3]);
    oh[1] = make_uint4(hbuf[4], hbuf[5], hbuf[6], hbuf[7]);
}

// ---------------------------------------------------------------------------
// Convs: mma.sync implicit-GEMM conv3x3, plain fp16, fp32 acc.
// Tile M=128 px, N=128 co, BK=64; 3 stages x 32KB => 2 CTAs/SM; distance-2.
// PHASE 2 fuses the to-RGB 1x1 conv (lane reduce + atomicAdd).
// ---------------------------------------------------------------------------
#define STAGE 32768
#define NSTAGE 3
#define DSMEM (NSTAGE*STAGE)
#define NITER 72

template<int PHASE>
__global__ void __launch_bounds__(256, 2)
conv_mma_kernel(const __half* __restrict__ aIn,
                const __half* __restrict__ wp,
                const float* __restrict__ dmod,
                const float* __restrict__ nscale,
                const float* __restrict__ noise,
                const float* __restrict__ sAux,   // PHASE1: s2 ; PHASE2: sr
                const float* __restrict__ rgbw,   // PHASE2 only
                __half* __restrict__ outA,        // PHASE1
                float* __restrict__ h_out,        // PHASE2
                float* __restrict__ rgb_out)      // PHASE2
{
    extern __shared__ __align__(128) char dsm[];
    __shared__ float e_d[128], e_ns[128], e_s2[128];
    __shared__ float e_wr[3][128];

    const int tid = threadIdx.x;
    const int lane = tid & 31;
    const int wid = tid >> 5;
    const int warp_m = wid & 1;
    const int warp_n = wid >> 1;
    const int co0 = blockIdx.x * 128;
    const int y0  = blockIdx.y * 2;
    const int b   = blockIdx.z;

    const uint32_t sb = smem_u32(dsm);

    if (tid < 128) {
        e_d[tid]  = dmod[b * CH + co0 + tid];
        e_ns[tid] = nscale[co0 + tid];
        if (PHASE == 1) {
            e_s2[tid] = sAux[b * CH + co0 + tid];
        } else {
            float sr = sAux[b * CH + co0 + tid];
            #pragma unroll
            for (int c = 0; c < 3; c++)
                e_wr[c][tid] = rgbw[c * CH + co0 + tid] * sr;
        }
    }

    float acc[4][4][4] = {};

    const int r0  = tid >> 3;
    const int col = tid & 7;
    const uint32_t baseAoff =
        (uint32_t)(((b * HP + y0) * WP + r0) * CPX + (col << 3));
    const uint32_t baseBoff =
        (uint32_t)(((co0 + r0) << 9) + (col << 3));
    const uint32_t dstA0 = (uint32_t)(r0 * 128 + ((col ^ (r0 & 7)) << 4));
    const uint32_t dstB0 = dstA0 + 16384u;
    const uint32_t AOFF1 = 32u * CPX;
    const uint32_t AOFF2 = (uint32_t)WP * CPX;

    auto issue = [&](int it, uint32_t bufOff) {
        const int tap = it >> 3;
        const int ci0 = (it & 7) << 6;
        const int dy = (tap * 171) >> 9;
        const int dx = tap - dy * 3;
        const __half* ga = aIn + baseAoff + (uint32_t)((dy * WP + dx) * CPX + ci0);
        const __half* gb = wp + baseBoff + (uint32_t)(tap * (CH * CH) + ci0);
        const uint32_t dA = sb + bufOff + dstA0;
        const uint32_t dB = sb + bufOff + dstB0;
        #pragma unroll
        for (int rep = 0; rep < 4; rep++) {
            const uint32_t ao = (rep & 1 ? AOFF1 : 0u) + (rep >> 1 ? AOFF2 : 0u);
            CP_ASYNC16(dA + rep * 4096, ga + ao);
            CP_ASYNC16(dB + rep * 4096, gb + rep * 16384);
        }
        CP_COMMIT();
    };

    issue(0, 0);
    issue(1, STAGE);

    const int laneHi = lane >> 4;
    uint32_t rowA[4], rsA[4], rowB[2], rsB[2];
    #pragma unroll
    for (int mt = 0; mt < 4; mt++) {
        int row = warp_m * 64 + mt * 16 + (lane & 15);
        rowA[mt] = (uint32_t)(row * 128);
        rsA[mt]  = (uint32_t)(row & 7);
    }
    #pragma unroll
    for (int nt = 0; nt < 2; nt++) {
        int row = warp_n * 32 + nt * 16 + (lane & 15);
        rowB[nt] = (uint32_t)(16384 + row * 128);
        rsB[nt]  = (uint32_t)(row & 7);
    }

    auto step = [&](int it, uint32_t curOff, uint32_t nxtOff) {
        CP_WAIT(1);
        __syncthreads();
        const uint32_t S = sb + curOff;
        #pragma unroll
        for (int ks = 0; ks < 4; ks++) {
            const uint32_t colA = (uint32_t)(ks * 2 + laneHi);
            uint32_t ah[4][4], bh[2][4];
            #pragma unroll
            for (int mt = 0; mt < 4; mt++)
                ldsm_x4(ah[mt], S + rowA[mt] + ((colA ^ rsA[mt]) << 4));
            #pragma unroll
            for (int nt = 0; nt < 2; nt++)
                ldsm_x4(bh[nt], S + rowB[nt] + ((colA ^ rsB[nt]) << 4));
            #pragma unroll
            for (int mt = 0; mt < 4; mt++)
                #pragma unroll
                for (int nt = 0; nt < 2; nt++)
                    #pragma unroll
                    for (int hf = 0; hf < 2; hf++)
                        mma_f16(acc[mt][nt * 2 + hf], ah[mt],
                                bh[nt][hf], bh[nt][hf + 2]);
            if (ks == 3 && it + 2 < NITER) issue(it + 2, nxtOff);
        }
    };

    #pragma unroll 1
    for (int it = 0; it < NITER; it += 3) {
        step(it,     0,         2 * STAGE);
        step(it + 1, STAGE,     0);
        step(it + 2, 2 * STAGE, STAGE);
    }

    // epilogue
    #pragma unroll
    for (int mt = 0; mt < 4; mt++) {
        #pragma unroll
        for (int rr = 0; rr < 2; rr++) {
            int m = warp_m * 64 + mt * 16 + rr * 8 + (lane >> 2);
            int py = y0 + (m >> 6);
            int px = m & 63;
            float nz = noise[(size_t)b * PLANE_O + py * WO + px];
            float rc0 = 0.f, rc1 = 0.f, rc2 = 0.f;
            #pragma unroll
            for (int nj = 0; nj < 4; nj++) {
                int nrel = warp_n * 32 + nj * 8 + (lane & 3) * 2;
                float v0 = acc[mt][nj][rr * 2 + 0] * e_d[nrel]     + e_ns[nrel]     * nz;
                float v1 = acc[mt][nj][rr * 2 + 1] * e_d[nrel + 1] + e_ns[nrel + 1] * nz;
                v0 = (v0 >= 0.f) ? v0 : 0.2f * v0;
                v1 = (v1 >= 0.f) ? v1 : 0.2f * v1;
                if (PHASE == 1) {
                    v0 *= e_s2[nrel];
                    v1 *= e_s2[nrel + 1];
                    size_t o = ((((size_t)b * HP + py + 1) * WP) + px + 1) * CPX + co0 + nrel;
                    *(uint32_t*)(outA + o) = pack_f16x2(__float2half(v0), __float2half(v1));
                } else {
                    size_t o = ((size_t)b * CH + co0 + nrel) * PLANE_O + py * WO + px;
                    h_out[o] = v0;
                    h_out[o + PLANE_O] = v1;
                    rc0 += e_wr[0][nrel] * v0 + e_wr[0][nrel + 1] * v1;
                    rc1 += e_wr[1][nrel] * v0 + e_wr[1][nrel + 1] * v1;
                    rc2 += e_wr[2][nrel] * v0 + e_wr[2][nrel + 1] * v1;
                }
            }
            if (PHASE == 2) {
                rc0 += __shfl_xor_sync(0xffffffffu, rc0, 1);
                rc0 += __shfl_xor_sync(0xffffffffu, rc0, 2);
                rc1 += __shfl_xor_sync(0xffffffffu, rc1, 1);
                rc1 += __shfl_xor_sync(0xffffffffu, rc1, 2);
                rc2 += __shfl_xor_sync(0xffffffffu, rc2, 1);
                rc2 += __shfl_xor_sync(0xffffffffu, rc2, 2);
                int lc = lane & 3;
                if (lc < 3) {
                    float rv = (lc == 0) ? rc0 : (lc == 1) ? rc1 : rc2;
                    atomicAdd(rgb_out + (size_t)b * 3 * PLANE_O + lc * PLANE_O
                              + py * WO + px, rv);
                }
            }
        }
    }
}

// ---------------------------------------------------------------------------
// host launch
// ---------------------------------------------------------------------------
extern "C" void kernel_launch(void* const* d_in, const int* in_sizes, int n_in,
                              void* d_out, int out_size)
{
    const float* x   = (const float*)d_in[0];
    const float* w   = (const float*)d_in[1];
    const float* w1  = (const float*)d_in[2];
    const float* m1w = (const float*)d_in[3];
    const float* m1b = (const float*)d_in[4];
    const float* ns1 = (const float*)d_in[5];
    const float* w2  = (const float*)d_in[6];
    const float* m2w = (const float*)d_in[7];
    const float* m2b = (const float*)d_in[8];
    const float* ns2 = (const float*)d_in[9];
    const float* wr  = (const float*)d_in[10];
    const float* mrw = (const float*)d_in[11];
    const float* mrb = (const float*)d_in[12];
    const float* n1  = (const float*)d_in[13];
    const float* n2  = (const float*)d_in[14];

    float* out     = (float*)d_out;
    float* h_out   = out;                                  // [8,512,64,64]
    float* rgb_out = out + (size_t)BATCH * CH * PLANE_O;   // [8,3,64,64]

    float *p_s2, *p_sr, *p_d1, *p_d2;
    __half *p_a1, *p_a2, *p_w1p, *p_w2p;
    cudaGetSymbolAddress((void**)&p_s2, g_s2);
    cudaGetSymbolAddress((void**)&p_sr, g_sr);
    cudaGetSymbolAddress((void**)&p_d1, g_d1);
    cudaGetSymbolAddress((void**)&p_d2, g_d2);
    cudaGetSymbolAddress((void**)&p_a1, g_a1);
    cudaGetSymbolAddress((void**)&p_a2, g_a2);
    cudaGetSymbolAddress((void**)&p_w1p, g_w1p);
    cudaGetSymbolAddress((void**)&p_w2p, g_w2p);

    cudaFuncSetAttribute(conv_mma_kernel<1>, cudaFuncAttributeMaxDynamicSharedMemorySize, DSMEM);
    cudaFuncSetAttribute(conv_mma_kernel<2>, cudaFuncAttributeMaxDynamicSharedMemorySize, DSMEM);

    // K0: styles + wpack(+wsq) + border-zero + rgb-zero
    prep1_kernel<<<K0_BLOCKS, 256>>>(w, m1w, m1b, m2w, m2b, mrw, mrb, w1, w2, rgb_out);
    // K1: demod + upsample
    prep2_kernel<<<K1_BLOCKS, 256>>>(x);
    // K2: conv1 (a1 -> a2, pre-modulated by s2)
    {
        dim3 g(4, 32, 8);
        conv_mma_kernel<1><<<g, 256, DSMEM>>>(p_a1, p_w1p, p_d1, ns1, n1,
                                              p_s2, nullptr, p_a2, nullptr, nullptr);
    }
    // K3: conv2 (a2 -> h_out fp32) + fused to-RGB
    {
        dim3 g(4, 32, 8);
        conv_mma_kernel<2><<<g, 256, DSMEM>>>(p_a2, p_w2p, p_d2, ns2, n2,
                                              p_sr, wr, nullptr, h_out, rgb_out);
    }
    (void)in_sizes; (void)n_in; (void)out_size;
}